// round 14
// baseline (speedup 1.0000x reference)
#include <cuda_runtime.h>
#include <cuda_fp16.h>
#include <cuda_bf16.h>
#include <cstdint>

#define MAX_N 100000
#define MAX_E 3200000
#define D 128
#define CAP 128   // fixed CSR bucket capacity per node (deg ~ Poisson(32))
#define SMS 136   // gemm smem row stride in halves

// Scratch
__device__ __half g_hs[(size_t)MAX_N * D];   // x@W1 (fp16), scaled by dinv in k_dinv_scale
__device__ float  g_h[(size_t)MAX_N * D];    // hidden after leaky (for pooling)
__device__ float  g_ss[MAX_N];               // dinv * (h @ W2)
__device__ float  g_dinv[MAX_N];
__device__ int    g_deg[MAX_N];
__device__ int    g_cur[MAX_N];              // scatter cursor (base = i*CAP)
__device__ int    g_csr[(size_t)MAX_N * CAP];// src ids, fixed buckets per dst
__device__ float  g_pool[64 * D];            // per-graph feature sums
__device__ int    g_gcount[64];              // nodes per graph

// ---------------------------------------------------------------------------
__global__ void k_zero(int N) {
    int i = blockIdx.x * blockDim.x + threadIdx.x;
    if (i < N) g_cur[i] = i * CAP;
    if (i < 64 * D) g_pool[i] = 0.f;
    if (i < 64) g_gcount[i] = 0;
}

// Scatter: 4 edges per thread via int4 loads -> 4 independent atomic chains.
__global__ void k_scatter(const int* __restrict__ ei, int E) {
    int e4 = blockIdx.x * blockDim.x + threadIdx.x;
    int e = e4 * 4;
    if (e >= E) return;
    if (e + 3 < E) {
        int4 s = __ldg((const int4*)(ei) + e4);
        int4 d = __ldg((const int4*)(ei + E) + e4);
        int p0 = atomicAdd(&g_cur[d.x], 1);
        int p1 = atomicAdd(&g_cur[d.y], 1);
        int p2 = atomicAdd(&g_cur[d.z], 1);
        int p3 = atomicAdd(&g_cur[d.w], 1);
        g_csr[p0] = s.x;
        g_csr[p1] = s.y;
        g_csr[p2] = s.z;
        g_csr[p3] = s.w;
    } else {
        for (int k = e; k < E; k++) {
            int src = __ldg(ei + k);
            int dst = __ldg(ei + E + k);
            int pos = atomicAdd(&g_cur[dst], 1);
            g_csr[pos] = src;
        }
    }
}

// ---------------------------------------------------------------------------
// Tensor-core GEMM chunk: rows [base, base + nrows). g_hs = fp16(x @ W1).
// ---------------------------------------------------------------------------
__global__ void __launch_bounds__(256) k_gemm_tc(const float* __restrict__ x,
                                                 const float* __restrict__ W,
                                                 int base, int N) {
    extern __shared__ __half sh[];
    __half* xh = sh;               // [128][SMS]
    __half* wt = sh + 128 * SMS;   // [128][SMS] W transposed (n, k)
    int tid = threadIdx.x;
    int row0 = base + blockIdx.x * 128;
    if (row0 >= N) return;

    const float4* x4 = (const float4*)x;
    #pragma unroll 4
    for (int i = tid; i < 4096; i += 256) {
        int r = i >> 5, c = (i & 31) * 4;
        float4 v = make_float4(0.f, 0.f, 0.f, 0.f);
        if (row0 + r < N) v = __ldg(x4 + (size_t)(row0 + r) * 32 + (c >> 2));
        __half2* p = (__half2*)&xh[r * SMS + c];
        p[0] = __floats2half2_rn(v.x, v.y);
        p[1] = __floats2half2_rn(v.z, v.w);
    }
    #pragma unroll 4
    for (int i = tid; i < 16384; i += 256) {
        int k = i >> 7, n = i & 127;
        wt[n * SMS + k] = __float2half_rn(__ldg(W + i));
    }
    __syncthreads();

    int wid = tid >> 5;
    int lane = tid & 31;
    int gid = lane >> 2;
    int tig = lane & 3;
    int wr0 = wid * 16;

    float acc[16][4];
    #pragma unroll
    for (int ng = 0; ng < 16; ng++)
        #pragma unroll
        for (int q = 0; q < 4; q++) acc[ng][q] = 0.f;

    const __half* arow_lo = xh + (wr0 + gid) * SMS;
    const __half* arow_hi = xh + (wr0 + gid + 8) * SMS;

    #pragma unroll
    for (int kc = 0; kc < 8; kc++) {
        int k0 = kc * 16;
        uint32_t a0 = *(const uint32_t*)(arow_lo + k0 + 2 * tig);
        uint32_t a1 = *(const uint32_t*)(arow_hi + k0 + 2 * tig);
        uint32_t a2 = *(const uint32_t*)(arow_lo + k0 + 2 * tig + 8);
        uint32_t a3 = *(const uint32_t*)(arow_hi + k0 + 2 * tig + 8);
        #pragma unroll
        for (int ng = 0; ng < 16; ng++) {
            const __half* brow = wt + (ng * 8 + gid) * SMS;
            uint32_t b0 = *(const uint32_t*)(brow + k0 + 2 * tig);
            uint32_t b1 = *(const uint32_t*)(brow + k0 + 2 * tig + 8);
            asm volatile(
                "mma.sync.aligned.m16n8k16.row.col.f32.f16.f16.f32 "
                "{%0,%1,%2,%3}, {%4,%5,%6,%7}, {%8,%9}, {%0,%1,%2,%3};"
                : "+f"(acc[ng][0]), "+f"(acc[ng][1]),
                  "+f"(acc[ng][2]), "+f"(acc[ng][3])
                : "r"(a0), "r"(a1), "r"(a2), "r"(a3), "r"(b0), "r"(b1));
        }
    }

    int r_lo = row0 + wr0 + gid;
    int r_hi = r_lo + 8;
    __half2* o_lo = (__half2*)(g_hs + (size_t)r_lo * D);
    __half2* o_hi = (__half2*)(g_hs + (size_t)r_hi * D);
    #pragma unroll
    for (int ng = 0; ng < 16; ng++) {
        int c = ng * 8 + 2 * tig;
        if (r_lo < N) o_lo[c >> 1] = __floats2half2_rn(acc[ng][0], acc[ng][1]);
        if (r_hi < N) o_hi[c >> 1] = __floats2half2_rn(acc[ng][2], acc[ng][3]);
    }
}

// ---------------------------------------------------------------------------
// dinv/deg from final cursors + in-place scale of hs by dinv. One warp/node.
// ---------------------------------------------------------------------------
__global__ void k_dinv_scale(int N) {
    int g = blockIdx.x * blockDim.x + threadIdx.x;
    int i = g >> 5;
    int lane = g & 31;
    if (i >= N) return;
    int d = g_cur[i] - i * CAP;
    float di = rsqrtf((float)d + 1.0f);
    if (lane == 0) { g_dinv[i] = di; g_deg[i] = d; }
    uint2* p = (uint2*)(g_hs + (size_t)i * D) + lane;
    uint2 v = *p;
    float2 f0 = __half22float2(*(__half2*)&v.x);
    float2 f1 = __half22float2(*(__half2*)&v.y);
    *(__half2*)&v.x = __floats2half2_rn(di * f0.x, di * f0.y);
    *(__half2*)&v.y = __floats2half2_rn(di * f1.x, di * f1.y);
    *p = v;
}

// ---------------------------------------------------------------------------
// Node aggregation + bias + leaky + h@W2. One warp per node, 8-deep pipeline.
// ---------------------------------------------------------------------------
__global__ void __launch_bounds__(256) k_node_agg(const float* __restrict__ b1,
                                                  const float* __restrict__ W2, int N) {
    int g = blockIdx.x * blockDim.x + threadIdx.x;
    int i = g >> 5;
    int lane = g & 31;
    if (i >= N) return;
    int cnt = g_deg[i];
    const int* csr = g_csr + (size_t)i * CAP;
    const uint2* hs2 = (const uint2*)g_hs;

    float4 acc = make_float4(0.f, 0.f, 0.f, 0.f);
    {
        uint2 rv = __ldg(hs2 + (size_t)i * 32 + lane);
        float2 f0 = __half22float2(*(const __half2*)&rv.x);
        float2 f1 = __half22float2(*(const __half2*)&rv.y);
        acc.x += f0.x; acc.y += f0.y; acc.z += f1.x; acc.w += f1.y;
    }
    int j = 0;
    for (; j + 8 <= cnt; j += 8) {
        int src[8];
        #pragma unroll
        for (int u = 0; u < 8; u++) src[u] = __ldg(csr + j + u);
        uint2 rv[8];
        #pragma unroll
        for (int u = 0; u < 8; u++) rv[u] = __ldg(hs2 + (size_t)src[u] * 32 + lane);
        #pragma unroll
        for (int u = 0; u < 8; u++) {
            float2 f0 = __half22float2(*(const __half2*)&rv[u].x);
            float2 f1 = __half22float2(*(const __half2*)&rv[u].y);
            acc.x += f0.x; acc.y += f0.y; acc.z += f1.x; acc.w += f1.y;
        }
    }
    for (; j < cnt; j++) {
        int src = __ldg(csr + j);
        uint2 rv = __ldg(hs2 + (size_t)src * 32 + lane);
        float2 f0 = __half22float2(*(const __half2*)&rv.x);
        float2 f1 = __half22float2(*(const __half2*)&rv.y);
        acc.x += f0.x; acc.y += f0.y; acc.z += f1.x; acc.w += f1.y;
    }

    float di = g_dinv[i];
    float4 b = __ldg(((const float4*)b1) + lane);
    float4 v;
    v.x = fmaf(di, acc.x, b.x);
    v.y = fmaf(di, acc.y, b.y);
    v.z = fmaf(di, acc.z, b.z);
    v.w = fmaf(di, acc.w, b.w);
    v.x = v.x > 0.f ? v.x : 0.01f * v.x;
    v.y = v.y > 0.f ? v.y : 0.01f * v.y;
    v.z = v.z > 0.f ? v.z : 0.01f * v.z;
    v.w = v.w > 0.f ? v.w : 0.01f * v.w;
    ((float4*)g_h)[(size_t)i * 32 + lane] = v;

    float4 w = __ldg(((const float4*)W2) + lane);
    float p = v.x * w.x + v.y * w.y + v.z * w.z + v.w * w.w;
    #pragma unroll
    for (int off = 16; off; off >>= 1) p += __shfl_xor_sync(0xffffffffu, p, off);
    if (lane == 0) g_ss[i] = di * p;
}

// ---------------------------------------------------------------------------
__global__ void k_leaf(const float* __restrict__ b2, float* __restrict__ out, int N) {
    int i = blockIdx.x * blockDim.x + threadIdx.x;
    if (i >= N) return;
    int cnt = g_deg[i];
    const int* csr = g_csr + (size_t)i * CAP;
    float sum = g_ss[i];
    int j = 0;
    for (; j + 8 <= cnt; j += 8) {
        int src[8];
        #pragma unroll
        for (int u = 0; u < 8; u++) src[u] = __ldg(csr + j + u);
        float sv[8];
        #pragma unroll
        for (int u = 0; u < 8; u++) sv[u] = __ldg(g_ss + src[u]);
        #pragma unroll
        for (int u = 0; u < 8; u++) sum += sv[u];
    }
    for (; j < cnt; j++) sum += __ldg(g_ss + __ldg(csr + j));
    out[i] = fmaf(g_dinv[i], sum, __ldg(b2));
}

// ---------------------------------------------------------------------------
__global__ void k_pool(const int* __restrict__ batch, int N) {
    int t = threadIdx.x;
    int n0 = blockIdx.x * 256;
    int n1 = min(n0 + 256, N);
    if (n0 >= N) return;
    int cur = __ldg(batch + n0);
    int runStart = n0;
    float sum = 0.f;
    for (int n = n0; n < n1; n++) {
        int bg = __ldg(batch + n);
        if (bg != cur) {
            atomicAdd(&g_pool[cur * D + t], sum);
            if (t == 0) atomicAdd(&g_gcount[cur], n - runStart);
            sum = 0.f; cur = bg; runStart = n;
        }
        sum += g_h[(size_t)n * D + t];
    }
    atomicAdd(&g_pool[cur * D + t], sum);
    if (t == 0) atomicAdd(&g_gcount[cur], n1 - runStart);
}

__global__ void k_eos(const float* __restrict__ W3, const float* __restrict__ b3,
                      float* __restrict__ out_eos) {
    int gph = blockIdx.x;
    int t = threadIdx.x;
    int cnt = g_gcount[gph];
    float denom = (float)(cnt > 0 ? cnt : 1);
    float val = (g_pool[gph * D + t] / denom) * __ldg(W3 + t);
    __shared__ float red[128];
    red[t] = val;
    __syncthreads();
    #pragma unroll
    for (int st = 64; st > 0; st >>= 1) {
        if (t < st) red[t] += red[t + st];
        __syncthreads();
    }
    if (t == 0) out_eos[gph] = red[0] + __ldg(b3);
}

// ---------------------------------------------------------------------------
extern "C" void kernel_launch(void* const* d_in, const int* in_sizes, int n_in,
                              void* d_out, int out_size) {
    const float* x     = (const float*)d_in[0];
    const int*   ei    = (const int*)d_in[1];
    const int*   batch = (const int*)d_in[2];
    const float* W1    = (const float*)d_in[3];
    const float* b1    = (const float*)d_in[4];
    const float* W2    = (const float*)d_in[5];
    const float* b2    = (const float*)d_in[6];
    const float* W3    = (const float*)d_in[7];
    const float* b3    = (const float*)d_in[8];
    float* out = (float*)d_out;

    int N = in_sizes[0] / D;
    int E = in_sizes[1] / 2;
    int G = out_size - N;

    int smem = 2 * 128 * SMS * (int)sizeof(__half);  // 69632B
    cudaFuncSetAttribute(k_gemm_tc, cudaFuncAttributeMaxDynamicSharedMemorySize, smem);

    static cudaStream_t s2 = nullptr;
    static cudaEvent_t eFork = nullptr, eJoin = nullptr, eAgg = nullptr, eTail = nullptr;
    if (!s2) {
        cudaStreamCreateWithFlags(&s2, cudaStreamNonBlocking);
        cudaEventCreateWithFlags(&eFork, cudaEventDisableTiming);
        cudaEventCreateWithFlags(&eJoin, cudaEventDisableTiming);
        cudaEventCreateWithFlags(&eAgg, cudaEventDisableTiming);
        cudaEventCreateWithFlags(&eTail, cudaEventDisableTiming);
    }

    // gemm split into 3 row-chunks (261+261+260 blocks of 128 rows).
    int blocksTotal = (N + 127) / 128;               // 782
    int bA = (blocksTotal + 2) / 3;                  // 261
    int bB = (blocksTotal - bA + 1) / 2;             // 261
    int bC = blocksTotal - bA - bB;                  // 260

    // Fork: main runs gemm chunks; s2 runs zero -> scatter -> (join).
    // Submission order: gemmA(0), gemmB(1), zero(2), scatter(3) <- profiled,
    // gemmC(4), ...
    cudaEventRecord(eFork, 0);
    cudaStreamWaitEvent(s2, eFork, 0);
    k_gemm_tc<<<bA, 256, smem>>>(x, W1, 0, N);                    // 0
    k_gemm_tc<<<bB, 256, smem>>>(x, W1, bA * 128, N);             // 1
    k_zero<<<(N + 255) / 256, 256, 0, s2>>>(N);                   // 2
    k_scatter<<<(E / 4 + 255) / 256, 256, 0, s2>>>(ei, E);        // 3 <- profiled
    k_gemm_tc<<<bC, 256, smem>>>(x, W1, (bA + bB) * 128, N);      // 4
    cudaEventRecord(eJoin, s2);
    cudaStreamWaitEvent(0, eJoin, 0);

    k_dinv_scale<<<(N * 32 + 255) / 256, 256>>>(N);
    k_node_agg<<<(N + 7) / 8, 256>>>(b1, W2, N);
    cudaEventRecord(eAgg, 0);

    // Tail fork: pool+eos on s2, leaf on main.
    cudaStreamWaitEvent(s2, eAgg, 0);
    k_pool<<<(N + 255) / 256, 128, 0, s2>>>(batch, N);
    k_eos<<<G, 128, 0, s2>>>(W3, b3, out + N);
    cudaEventRecord(eTail, s2);

    k_leaf<<<(N + 255) / 256, 256>>>(b2, out, N);
    cudaStreamWaitEvent(0, eTail, 0);
}

// round 15
// speedup vs baseline: 1.4038x; 1.4038x over previous
#include <cuda_runtime.h>
#include <cuda_fp16.h>
#include <cuda_bf16.h>
#include <cstdint>

#define MAX_N 100000
#define MAX_E 3200000
#define D 128
#define CAP 128   // fixed CSR bucket capacity per node (deg ~ Poisson(32))
#define SMS 136   // gemm smem row stride in halves

// Scratch
__device__ __half g_hs[(size_t)MAX_N * D];   // x@W1 (fp16), scaled by dinv in k_dinv_scale
__device__ float  g_h[(size_t)MAX_N * D];    // hidden after leaky (for pooling)
__device__ float  g_ss[MAX_N];               // dinv * (h @ W2)
__device__ float  g_dinv[MAX_N];
__device__ int    g_deg[MAX_N];
__device__ int    g_cur[MAX_N];              // scatter cursor (base = i*CAP)
__device__ int    g_csr[(size_t)MAX_N * CAP];// src ids, fixed buckets per dst
__device__ float  g_pool[64 * D];            // per-graph feature sums
__device__ int    g_gcount[64];              // nodes per graph

// ---------------------------------------------------------------------------
__global__ void k_zero(int N) {
    int i = blockIdx.x * blockDim.x + threadIdx.x;
    if (i < N) g_cur[i] = i * CAP;
    if (i < 64 * D) g_pool[i] = 0.f;
    if (i < 64) g_gcount[i] = 0;
}

// Scatter: 4 edges per thread via int4 loads -> 4 independent atomic chains.
__global__ void k_scatter(const int* __restrict__ ei, int E) {
    int e4 = blockIdx.x * blockDim.x + threadIdx.x;
    int e = e4 * 4;
    if (e >= E) return;
    if (e + 3 < E) {
        int4 s = __ldg((const int4*)(ei) + e4);
        int4 d = __ldg((const int4*)(ei + E) + e4);
        int p0 = atomicAdd(&g_cur[d.x], 1);
        int p1 = atomicAdd(&g_cur[d.y], 1);
        int p2 = atomicAdd(&g_cur[d.z], 1);
        int p3 = atomicAdd(&g_cur[d.w], 1);
        g_csr[p0] = s.x;
        g_csr[p1] = s.y;
        g_csr[p2] = s.z;
        g_csr[p3] = s.w;
    } else {
        for (int k = e; k < E; k++) {
            int src = __ldg(ei + k);
            int dst = __ldg(ei + E + k);
            int pos = atomicAdd(&g_cur[dst], 1);
            g_csr[pos] = src;
        }
    }
}

// ---------------------------------------------------------------------------
// Tensor-core GEMM chunk: rows [base, ...). g_hs = fp16(x @ W1), unscaled.
// ---------------------------------------------------------------------------
__global__ void __launch_bounds__(256) k_gemm_tc(const float* __restrict__ x,
                                                 const float* __restrict__ W,
                                                 int base, int N) {
    extern __shared__ __half sh[];
    __half* xh = sh;               // [128][SMS]
    __half* wt = sh + 128 * SMS;   // [128][SMS] W transposed (n, k)
    int tid = threadIdx.x;
    int row0 = base + blockIdx.x * 128;
    if (row0 >= N) return;

    const float4* x4 = (const float4*)x;
    #pragma unroll 4
    for (int i = tid; i < 4096; i += 256) {
        int r = i >> 5, c = (i & 31) * 4;
        float4 v = make_float4(0.f, 0.f, 0.f, 0.f);
        if (row0 + r < N) v = __ldg(x4 + (size_t)(row0 + r) * 32 + (c >> 2));
        __half2* p = (__half2*)&xh[r * SMS + c];
        p[0] = __floats2half2_rn(v.x, v.y);
        p[1] = __floats2half2_rn(v.z, v.w);
    }
    #pragma unroll 4
    for (int i = tid; i < 16384; i += 256) {
        int k = i >> 7, n = i & 127;
        wt[n * SMS + k] = __float2half_rn(__ldg(W + i));
    }
    __syncthreads();

    int wid = tid >> 5;
    int lane = tid & 31;
    int gid = lane >> 2;
    int tig = lane & 3;
    int wr0 = wid * 16;

    float acc[16][4];
    #pragma unroll
    for (int ng = 0; ng < 16; ng++)
        #pragma unroll
        for (int q = 0; q < 4; q++) acc[ng][q] = 0.f;

    const __half* arow_lo = xh + (wr0 + gid) * SMS;
    const __half* arow_hi = xh + (wr0 + gid + 8) * SMS;

    #pragma unroll
    for (int kc = 0; kc < 8; kc++) {
        int k0 = kc * 16;
        uint32_t a0 = *(const uint32_t*)(arow_lo + k0 + 2 * tig);
        uint32_t a1 = *(const uint32_t*)(arow_hi + k0 + 2 * tig);
        uint32_t a2 = *(const uint32_t*)(arow_lo + k0 + 2 * tig + 8);
        uint32_t a3 = *(const uint32_t*)(arow_hi + k0 + 2 * tig + 8);
        #pragma unroll
        for (int ng = 0; ng < 16; ng++) {
            const __half* brow = wt + (ng * 8 + gid) * SMS;
            uint32_t b0 = *(const uint32_t*)(brow + k0 + 2 * tig);
            uint32_t b1 = *(const uint32_t*)(brow + k0 + 2 * tig + 8);
            asm volatile(
                "mma.sync.aligned.m16n8k16.row.col.f32.f16.f16.f32 "
                "{%0,%1,%2,%3}, {%4,%5,%6,%7}, {%8,%9}, {%0,%1,%2,%3};"
                : "+f"(acc[ng][0]), "+f"(acc[ng][1]),
                  "+f"(acc[ng][2]), "+f"(acc[ng][3])
                : "r"(a0), "r"(a1), "r"(a2), "r"(a3), "r"(b0), "r"(b1));
        }
    }

    int r_lo = row0 + wr0 + gid;
    int r_hi = r_lo + 8;
    __half2* o_lo = (__half2*)(g_hs + (size_t)r_lo * D);
    __half2* o_hi = (__half2*)(g_hs + (size_t)r_hi * D);
    #pragma unroll
    for (int ng = 0; ng < 16; ng++) {
        int c = ng * 8 + 2 * tig;
        if (r_lo < N) o_lo[c >> 1] = __floats2half2_rn(acc[ng][0], acc[ng][1]);
        if (r_hi < N) o_hi[c >> 1] = __floats2half2_rn(acc[ng][2], acc[ng][3]);
    }
}

// ---------------------------------------------------------------------------
// dinv/deg from final cursors + in-place scale of hs by dinv. One warp/node.
// ---------------------------------------------------------------------------
__global__ void k_dinv_scale(int N) {
    int g = blockIdx.x * blockDim.x + threadIdx.x;
    int i = g >> 5;
    int lane = g & 31;
    if (i >= N) return;
    int d = g_cur[i] - i * CAP;
    float di = rsqrtf((float)d + 1.0f);
    if (lane == 0) { g_dinv[i] = di; g_deg[i] = d; }
    uint2* p = (uint2*)(g_hs + (size_t)i * D) + lane;
    uint2 v = *p;
    float2 f0 = __half22float2(*(__half2*)&v.x);
    float2 f1 = __half22float2(*(__half2*)&v.y);
    *(__half2*)&v.x = __floats2half2_rn(di * f0.x, di * f0.y);
    *(__half2*)&v.y = __floats2half2_rn(di * f1.x, di * f1.y);
    *p = v;
}

// ---------------------------------------------------------------------------
// Node aggregation + bias + leaky + h@W2. One warp per node, 8-deep pipeline.
// ---------------------------------------------------------------------------
__global__ void __launch_bounds__(256) k_node_agg(const float* __restrict__ b1,
                                                  const float* __restrict__ W2, int N) {
    int g = blockIdx.x * blockDim.x + threadIdx.x;
    int i = g >> 5;
    int lane = g & 31;
    if (i >= N) return;
    int cnt = g_deg[i];
    const int* csr = g_csr + (size_t)i * CAP;
    const uint2* hs2 = (const uint2*)g_hs;

    float4 acc = make_float4(0.f, 0.f, 0.f, 0.f);
    {
        uint2 rv = __ldg(hs2 + (size_t)i * 32 + lane);
        float2 f0 = __half22float2(*(const __half2*)&rv.x);
        float2 f1 = __half22float2(*(const __half2*)&rv.y);
        acc.x += f0.x; acc.y += f0.y; acc.z += f1.x; acc.w += f1.y;
    }
    int j = 0;
    for (; j + 8 <= cnt; j += 8) {
        int src[8];
        #pragma unroll
        for (int u = 0; u < 8; u++) src[u] = __ldg(csr + j + u);
        uint2 rv[8];
        #pragma unroll
        for (int u = 0; u < 8; u++) rv[u] = __ldg(hs2 + (size_t)src[u] * 32 + lane);
        #pragma unroll
        for (int u = 0; u < 8; u++) {
            float2 f0 = __half22float2(*(const __half2*)&rv[u].x);
            float2 f1 = __half22float2(*(const __half2*)&rv[u].y);
            acc.x += f0.x; acc.y += f0.y; acc.z += f1.x; acc.w += f1.y;
        }
    }
    for (; j < cnt; j++) {
        int src = __ldg(csr + j);
        uint2 rv = __ldg(hs2 + (size_t)src * 32 + lane);
        float2 f0 = __half22float2(*(const __half2*)&rv.x);
        float2 f1 = __half22float2(*(const __half2*)&rv.y);
        acc.x += f0.x; acc.y += f0.y; acc.z += f1.x; acc.w += f1.y;
    }

    float di = g_dinv[i];
    float4 b = __ldg(((const float4*)b1) + lane);
    float4 v;
    v.x = fmaf(di, acc.x, b.x);
    v.y = fmaf(di, acc.y, b.y);
    v.z = fmaf(di, acc.z, b.z);
    v.w = fmaf(di, acc.w, b.w);
    v.x = v.x > 0.f ? v.x : 0.01f * v.x;
    v.y = v.y > 0.f ? v.y : 0.01f * v.y;
    v.z = v.z > 0.f ? v.z : 0.01f * v.z;
    v.w = v.w > 0.f ? v.w : 0.01f * v.w;
    ((float4*)g_h)[(size_t)i * 32 + lane] = v;

    float4 w = __ldg(((const float4*)W2) + lane);
    float p = v.x * w.x + v.y * w.y + v.z * w.z + v.w * w.w;
    #pragma unroll
    for (int off = 16; off; off >>= 1) p += __shfl_xor_sync(0xffffffffu, p, off);
    if (lane == 0) g_ss[i] = di * p;
}

// ---------------------------------------------------------------------------
__global__ void k_leaf(const float* __restrict__ b2, float* __restrict__ out, int N) {
    int i = blockIdx.x * blockDim.x + threadIdx.x;
    if (i >= N) return;
    int cnt = g_deg[i];
    const int* csr = g_csr + (size_t)i * CAP;
    float sum = g_ss[i];
    int j = 0;
    for (; j + 8 <= cnt; j += 8) {
        int src[8];
        #pragma unroll
        for (int u = 0; u < 8; u++) src[u] = __ldg(csr + j + u);
        float sv[8];
        #pragma unroll
        for (int u = 0; u < 8; u++) sv[u] = __ldg(g_ss + src[u]);
        #pragma unroll
        for (int u = 0; u < 8; u++) sum += sv[u];
    }
    for (; j < cnt; j++) sum += __ldg(g_ss + __ldg(csr + j));
    out[i] = fmaf(g_dinv[i], sum, __ldg(b2));
}

// ---------------------------------------------------------------------------
// Pool: 64 nodes/block, 128 threads (one per feature). Loads batched 8-deep
// into registers BEFORE the branchy run-flush accumulate -> MLP 8.
// ---------------------------------------------------------------------------
__global__ void k_pool(const int* __restrict__ batch, int N) {
    int t = threadIdx.x;
    int n0 = blockIdx.x * 64;
    if (n0 >= N) return;
    int n1 = min(n0 + 64, N);
    int cnt = n1 - n0;

    __shared__ int sb[64];
    if (t < 64) sb[t] = (n0 + t < N) ? __ldg(batch + n0 + t) : -1;
    __syncthreads();

    int cur = sb[0];
    int runStart = n0;
    float sum = 0.f;
    for (int base = 0; base < cnt; base += 8) {
        int m = min(8, cnt - base);
        float v[8];
        #pragma unroll
        for (int u = 0; u < 8; u++)
            v[u] = (u < m) ? __ldg(g_h + (size_t)(n0 + base + u) * D + t) : 0.f;
        #pragma unroll
        for (int u = 0; u < 8; u++) {
            if (u < m) {
                int n = n0 + base + u;
                int bg = sb[base + u];
                if (bg != cur) {
                    atomicAdd(&g_pool[cur * D + t], sum);
                    if (t == 0) atomicAdd(&g_gcount[cur], n - runStart);
                    sum = 0.f; cur = bg; runStart = n;
                }
                sum += v[u];
            }
        }
    }
    atomicAdd(&g_pool[cur * D + t], sum);
    if (t == 0) atomicAdd(&g_gcount[cur], n1 - runStart);
}

__global__ void k_eos(const float* __restrict__ W3, const float* __restrict__ b3,
                      float* __restrict__ out_eos) {
    int gph = blockIdx.x;
    int t = threadIdx.x;
    int cnt = g_gcount[gph];
    float denom = (float)(cnt > 0 ? cnt : 1);
    float val = (g_pool[gph * D + t] / denom) * __ldg(W3 + t);
    __shared__ float red[128];
    red[t] = val;
    __syncthreads();
    #pragma unroll
    for (int st = 64; st > 0; st >>= 1) {
        if (t < st) red[t] += red[t + st];
        __syncthreads();
    }
    if (t == 0) out_eos[gph] = red[0] + __ldg(b3);
}

// ---------------------------------------------------------------------------
extern "C" void kernel_launch(void* const* d_in, const int* in_sizes, int n_in,
                              void* d_out, int out_size) {
    const float* x     = (const float*)d_in[0];
    const int*   ei    = (const int*)d_in[1];
    const int*   batch = (const int*)d_in[2];
    const float* W1    = (const float*)d_in[3];
    const float* b1    = (const float*)d_in[4];
    const float* W2    = (const float*)d_in[5];
    const float* b2    = (const float*)d_in[6];
    const float* W3    = (const float*)d_in[7];
    const float* b3    = (const float*)d_in[8];
    float* out = (float*)d_out;

    int N = in_sizes[0] / D;
    int E = in_sizes[1] / 2;
    int G = out_size - N;

    int smem = 2 * 128 * SMS * (int)sizeof(__half);  // 69632B
    cudaFuncSetAttribute(k_gemm_tc, cudaFuncAttributeMaxDynamicSharedMemorySize, smem);

    static cudaStream_t s2 = nullptr;
    static cudaEvent_t eFork = nullptr, eJoin = nullptr, eAgg = nullptr, eTail = nullptr;
    if (!s2) {
        cudaStreamCreateWithFlags(&s2, cudaStreamNonBlocking);
        cudaEventCreateWithFlags(&eFork, cudaEventDisableTiming);
        cudaEventCreateWithFlags(&eJoin, cudaEventDisableTiming);
        cudaEventCreateWithFlags(&eAgg, cudaEventDisableTiming);
        cudaEventCreateWithFlags(&eTail, cudaEventDisableTiming);
    }

    int blocksTotal = (N + 127) / 128;
    int bA = (blocksTotal + 2) / 3;
    int bB = (blocksTotal - bA + 1) / 2;
    int bC = blocksTotal - bA - bB;

    // Fork: main runs gemm chunks; s2 runs zero -> scatter.
    cudaEventRecord(eFork, 0);
    cudaStreamWaitEvent(s2, eFork, 0);
    k_gemm_tc<<<bA, 256, smem>>>(x, W1, 0, N);
    k_gemm_tc<<<bB, 256, smem>>>(x, W1, bA * 128, N);
    k_zero<<<(N + 255) / 256, 256, 0, s2>>>(N);
    k_scatter<<<(E / 4 + 255) / 256, 256, 0, s2>>>(ei, E);
    k_gemm_tc<<<bC, 256, smem>>>(x, W1, (bA + bB) * 128, N);
    cudaEventRecord(eJoin, s2);
    cudaStreamWaitEvent(0, eJoin, 0);

    k_dinv_scale<<<(N * 32 + 255) / 256, 256>>>(N);
    k_node_agg<<<(N + 7) / 8, 256>>>(b1, W2, N);
    cudaEventRecord(eAgg, 0);

    // Tail fork: pool+eos on s2, leaf on main.
    cudaStreamWaitEvent(s2, eAgg, 0);
    k_pool<<<(N + 63) / 64, 128, 0, s2>>>(batch, N);
    k_eos<<<G, 128, 0, s2>>>(W3, b3, out + N);
    cudaEventRecord(eTail, s2);

    k_leaf<<<(N + 255) / 256, 256>>>(b2, out, N);
    cudaStreamWaitEvent(0, eTail, 0);
}